// round 5
// baseline (speedup 1.0000x reference)
#include <cuda_runtime.h>
#include <cstdint>
#include <cstddef>

// Problem constants
#define NB   8
#define CIN  64
#define COUT 64
#define HH   128
#define WW   128
#define NCTX 16
#define KK9  9

// ---------------------------------------------------------------------------
// Device scratch
// ---------------------------------------------------------------------------
__device__ float g_meanx[NB * CIN];
__device__ float g_ctxvec[NB * NCTX];
__device__ float g_W2[NB * CIN * KK9 * COUT];   // [b][c_in][kk][oc]

// ---------------------------------------------------------------------------
// packed f32x2 helpers
// ---------------------------------------------------------------------------
typedef unsigned long long u64;

static __device__ __forceinline__ u64 fma2(u64 a, u64 b, u64 d) {
    asm("fma.rn.f32x2 %0, %1, %2, %0;" : "+l"(d) : "l"(a), "l"(b));
    return d;
}
static __device__ __forceinline__ u64 pack2(float lo, float hi) {
    u64 r; asm("mov.b64 %0, {%1, %2};" : "=l"(r) : "f"(lo), "f"(hi)); return r;
}
static __device__ __forceinline__ float2 unpack2(u64 v) {
    float2 r; asm("mov.b64 {%0, %1}, %2;" : "=f"(r.x), "=f"(r.y) : "l"(v)); return r;
}

// ---------------------------------------------------------------------------
// K1: mean over H*W for each (b,c) plane. 512 blocks x 256 threads.
// ---------------------------------------------------------------------------
__global__ void k_mean(const float* __restrict__ x) {
    const int plane = blockIdx.x;
    const float4* xp = (const float4*)(x + (size_t)plane * (HH * WW));
    float s = 0.f;
    for (int i = threadIdx.x; i < (HH * WW) / 4; i += 256) {
        float4 v = xp[i];
        s += (v.x + v.y) + (v.z + v.w);
    }
    __shared__ float red[8];
    #pragma unroll
    for (int o = 16; o; o >>= 1) s += __shfl_down_sync(0xffffffffu, s, o);
    if ((threadIdx.x & 31) == 0) red[threadIdx.x >> 5] = s;
    __syncthreads();
    if (threadIdx.x == 0) {
        float t = 0.f;
        #pragma unroll
        for (int i = 0; i < 8; i++) t += red[i];
        g_meanx[plane] = t * (1.0f / (HH * WW));
    }
}

// ---------------------------------------------------------------------------
// K2: ctx_vec = ctx_w . meanx + ctx_b
// ---------------------------------------------------------------------------
__global__ void k_ctx(const float* __restrict__ ctx_w, const float* __restrict__ ctx_b) {
    const int t = threadIdx.x;
    const int b = t >> 4;
    const int j = t & 15;
    float s = ctx_b[j];
    #pragma unroll 16
    for (int c = 0; c < CIN; c++) s += g_meanx[b * CIN + c] * ctx_w[j * CIN + c];
    g_ctxvec[t] = s;
}

// ---------------------------------------------------------------------------
// K3: generate + tanh + mean-center + compose with value_w.
// ---------------------------------------------------------------------------
__global__ void k_gen(const float* __restrict__ kg_w, const float* __restrict__ kg_b,
                      const float* __restrict__ gamma, const float* __restrict__ value_w) {
    const int b = blockIdx.x >> 6;
    const int o = blockIdx.x & 63;
    const int t = threadIdx.x;            // 0..575

    __shared__ float Wsh[576];
    __shared__ float red[18];
    __shared__ float smean;

    float cv[NCTX];
    #pragma unroll
    for (int j = 0; j < NCTX; j++) cv[j] = g_ctxvec[b * NCTX + j];

    const int idx = o * 576 + t;
    const float4* wr = (const float4*)(kg_w + (size_t)idx * NCTX);
    float s = kg_b[idx];
    #pragma unroll
    for (int q = 0; q < 4; q++) {
        float4 w = wr[q];
        s += cv[q * 4 + 0] * w.x + cv[q * 4 + 1] * w.y +
             cv[q * 4 + 2] * w.z + cv[q * 4 + 3] * w.w;
    }
    const float v = tanhf(s);

    float r = v;
    #pragma unroll
    for (int off = 16; off; off >>= 1) r += __shfl_down_sync(0xffffffffu, r, off);
    if ((t & 31) == 0) red[t >> 5] = r;
    __syncthreads();
    if (t == 0) {
        float tt = 0.f;
        #pragma unroll
        for (int i = 0; i < 18; i++) tt += red[i];
        smean = tt * (1.0f / 576.0f);
    }
    __syncthreads();

    const float lam = 1.0f / (1.0f + expf(-gamma[o]));
    Wsh[t] = v - lam * smean;
    __syncthreads();

    const int c2 = t / 9;
    const int kk = t - c2 * 9;
    float acc = 0.f;
    #pragma unroll 8
    for (int c = 0; c < CIN; c++)
        acc += Wsh[c * 9 + kk] * value_w[c * CIN + c2];

    g_W2[(((size_t)b * CIN + c2) * KK9 + kk) * COUT + o] = acc;
}

// ---------------------------------------------------------------------------
// K4: main conv, packed f32x2 FMA inner loop.
// Block 128 thr: tile 16 rows x 32 cols x 16 oc. Thread: 4 oc x 16 px
// (= 4 oc x 8 pixel-pairs). Weights held splatted (w,w) in smem.
// ---------------------------------------------------------------------------
__global__ void __launch_bounds__(128) k_conv(const float* __restrict__ x,
                                              const float* __restrict__ bias,
                                              float* __restrict__ out) {
    __shared__ float  sin_[8][18][36];          // input tile chunk (+pad)
    __shared__ float2 sw2[8 * KK9 * 16];        // splatted weights (w,w)

    const int tid = threadIdx.x;
    const int tc  = blockIdx.x;
    const int tr  = blockIdx.y;
    const int b   = blockIdx.z >> 2;
    const int ocg = blockIdx.z & 3;
    const int r0  = tr * 16;
    const int c0  = tc * 32;

    const int og  = tid & 3;              // 4 oc each
    const int pg  = tid >> 2;
    const int pr  = pg >> 1;              // output row in tile
    const int pc0 = (pg & 1) * 16;        // output col base (even)

    u64 acc[4][8];                        // [oc][pixel-pair]
    #pragma unroll
    for (int i = 0; i < 4; i++)
        #pragma unroll
        for (int q = 0; q < 8; q++) acc[i][q] = 0ull;

    for (int ch = 0; ch < 8; ch++) {
        const int cc0 = ch * 8;

        // input tile chunk: 8 ch x 18 rows x 34 cols (zero pad)
        for (int i = tid; i < 8 * 18 * 34; i += 128) {
            const int cc  = i / 612;
            const int rem = i - cc * 612;
            const int ri  = rem / 34;
            const int ci  = rem - ri * 34;
            const int gr  = r0 - 1 + ri;
            const int gc  = c0 - 1 + ci;
            float v = 0.f;
            if ((unsigned)gr < 128u && (unsigned)gc < 128u)
                v = x[(((size_t)b * CIN + cc0 + cc) * HH + gr) * WW + gc];
            sin_[cc][ri][ci] = v;
        }
        // weights, written as splatted pairs
        for (int j = tid; j < 1152; j += 128) {
            const int cc = j / 144;
            const int r2 = j - cc * 144;
            const float w = g_W2[(((size_t)b * CIN + cc0 + cc) * KK9 + (r2 >> 4)) * COUT
                                 + ocg * 16 + (r2 & 15)];
            sw2[j] = make_float2(w, w);
        }
        __syncthreads();

        #pragma unroll 1
        for (int cc = 0; cc < 8; cc++) {
            #pragma unroll
            for (int kh = 0; kh < 3; kh++) {
                // row of 18 inputs
                float in[18];
                const float4* rp = (const float4*)&sin_[cc][pr + kh][pc0];
                *(float4*)&in[0]  = rp[0];
                *(float4*)&in[4]  = rp[1];
                *(float4*)&in[8]  = rp[2];
                *(float4*)&in[12] = rp[3];
                in[16] = sin_[cc][pr + kh][pc0 + 16];
                in[17] = sin_[cc][pr + kh][pc0 + 17];

                // splatted weights: 3 kw x 4 oc
                u64 w0[4], w1[4], w2[4];
                {
                    const float2* wp = &sw2[(cc * 9 + kh * 3) * 16 + og * 4];
                    #pragma unroll
                    for (int i = 0; i < 4; i++) {
                        w0[i] = *(const u64*)&wp[i];
                        w1[i] = *(const u64*)&wp[16 + i];
                        w2[i] = *(const u64*)&wp[32 + i];
                    }
                }

                u64 e = pack2(in[0], in[1]);
                #pragma unroll
                for (int q = 0; q < 8; q++) {
                    const u64 o_ = pack2(in[2 * q + 1], in[2 * q + 2]);
                    const u64 e1 = pack2(in[2 * q + 2], in[2 * q + 3]);
                    #pragma unroll
                    for (int i = 0; i < 4; i++) {
                        acc[i][q] = fma2(e,  w0[i], acc[i][q]);
                        acc[i][q] = fma2(o_, w1[i], acc[i][q]);
                        acc[i][q] = fma2(e1, w2[i], acc[i][q]);
                    }
                    e = e1;
                }
            }
        }
        __syncthreads();
    }

    // epilogue: +bias, ReLU, float4 stores
    #pragma unroll
    for (int i = 0; i < 4; i++) {
        const int oc = ocg * 16 + og * 4 + i;
        const float bv = bias[oc];
        float* op = out + ((((size_t)b * COUT + oc) * HH + (r0 + pr)) * WW + (c0 + pc0));
        #pragma unroll
        for (int q2 = 0; q2 < 4; q2++) {
            const float2 a = unpack2(acc[i][2 * q2]);
            const float2 c = unpack2(acc[i][2 * q2 + 1]);
            float4 vv;
            vv.x = fmaxf(a.x + bv, 0.f);
            vv.y = fmaxf(a.y + bv, 0.f);
            vv.z = fmaxf(c.x + bv, 0.f);
            vv.w = fmaxf(c.y + bv, 0.f);
            ((float4*)op)[q2] = vv;
        }
    }
}

// ---------------------------------------------------------------------------
// Launch
// ---------------------------------------------------------------------------
extern "C" void kernel_launch(void* const* d_in, const int* in_sizes, int n_in,
                              void* d_out, int out_size) {
    const float* x       = (const float*)d_in[0];
    const float* ctx_w   = (const float*)d_in[1];
    const float* ctx_b   = (const float*)d_in[2];
    const float* kg_w    = (const float*)d_in[3];
    const float* kg_b    = (const float*)d_in[4];
    const float* gamma   = (const float*)d_in[5];
    const float* bias    = (const float*)d_in[6];
    const float* value_w = (const float*)d_in[7];
    float* out = (float*)d_out;

    k_mean<<<NB * CIN, 256>>>(x);
    k_ctx<<<1, 128>>>(ctx_w, ctx_b);
    k_gen<<<NB * COUT, 576>>>(kg_w, kg_b, gamma, value_w);

    dim3 grid(4, 8, NB * 4);
    k_conv<<<grid, 128>>>(x, bias, out);
}

// round 8
// speedup vs baseline: 1.4967x; 1.4967x over previous
#include <cuda_runtime.h>
#include <cstdint>
#include <cstddef>

// Problem constants
#define NB   8
#define CIN  64
#define COUT 64
#define HH   128
#define WW   128
#define NCTX 16
#define KTOT 576          // CIN*9
#define NKS  72           // k-steps of 8
#define RAWC 136          // padded raw row: cols [0..3]=0, 4..131=img, 132..135=0
#define NROWS6 (6*RAWC)

// ---------------------------------------------------------------------------
// Device scratch
// ---------------------------------------------------------------------------
__device__ float g_meanx[NB * CIN];
__device__ float g_ctxvec[NB * NCTX];
__device__ float g_W2[NB * KTOT * COUT];        // [b][k][oc], k = c*9+kh*3+kw

// ---------------------------------------------------------------------------
// helpers
// ---------------------------------------------------------------------------
static __device__ __forceinline__ uint32_t tf32_rna(float a) {
    uint32_t r; asm("cvt.rna.tf32.f32 %0, %1;" : "=r"(r) : "f"(a)); return r;
}

static __device__ __forceinline__ void mma8(float* d, uint32_t a0, uint32_t a1,
                                            uint32_t a2, uint32_t a3,
                                            uint32_t b0, uint32_t b1) {
    asm volatile(
        "mma.sync.aligned.m16n8k8.row.col.f32.tf32.tf32.f32 "
        "{%0,%1,%2,%3}, {%4,%5,%6,%7}, {%8,%9}, {%0,%1,%2,%3};"
        : "+f"(d[0]), "+f"(d[1]), "+f"(d[2]), "+f"(d[3])
        : "r"(a0), "r"(a1), "r"(a2), "r"(a3), "r"(b0), "r"(b1));
}

// ---------------------------------------------------------------------------
// SMEM layout (bytes)
// ---------------------------------------------------------------------------
#define OFF_TBL2 0                       // 288 u32 = 1152 B
#define OFF_BF   2048                    // 72*4*32 uint4 = 147456 B
#define OFF_RAW  149504                  // 16*6*136*4 = 52224 B
#define SMEM_TOTAL 201728

// ---------------------------------------------------------------------------
// K1: mean over H*W per (b,c) plane
// ---------------------------------------------------------------------------
__global__ void k_mean(const float* __restrict__ x) {
    const int plane = blockIdx.x;
    const float4* xp = (const float4*)(x + (size_t)plane * (HH * WW));
    float s = 0.f;
    for (int i = threadIdx.x; i < (HH * WW) / 4; i += 256) {
        float4 v = xp[i];
        s += (v.x + v.y) + (v.z + v.w);
    }
    __shared__ float red[8];
    #pragma unroll
    for (int o = 16; o; o >>= 1) s += __shfl_down_sync(0xffffffffu, s, o);
    if ((threadIdx.x & 31) == 0) red[threadIdx.x >> 5] = s;
    __syncthreads();
    if (threadIdx.x == 0) {
        float t = 0.f;
        #pragma unroll
        for (int i = 0; i < 8; i++) t += red[i];
        g_meanx[plane] = t * (1.0f / (HH * WW));
    }
}

// ---------------------------------------------------------------------------
// K2: ctx_vec
// ---------------------------------------------------------------------------
__global__ void k_ctx(const float* __restrict__ ctx_w, const float* __restrict__ ctx_b) {
    const int t = threadIdx.x;
    const int b = t >> 4;
    const int j = t & 15;
    float s = ctx_b[j];
    #pragma unroll 16
    for (int c = 0; c < CIN; c++) s += g_meanx[b * CIN + c] * ctx_w[j * CIN + c];
    g_ctxvec[t] = s;
}

// ---------------------------------------------------------------------------
// K3: generate + tanh + mean-center + compose with value_w
// ---------------------------------------------------------------------------
__global__ void k_gen(const float* __restrict__ kg_w, const float* __restrict__ kg_b,
                      const float* __restrict__ gamma, const float* __restrict__ value_w) {
    const int b = blockIdx.x >> 6;
    const int o = blockIdx.x & 63;
    const int t = threadIdx.x;            // 0..575

    __shared__ float Wsh[576];
    __shared__ float red[18];
    __shared__ float smean;

    float cv[NCTX];
    #pragma unroll
    for (int j = 0; j < NCTX; j++) cv[j] = g_ctxvec[b * NCTX + j];

    const int idx = o * 576 + t;
    const float4* wr = (const float4*)(kg_w + (size_t)idx * NCTX);
    float s = kg_b[idx];
    #pragma unroll
    for (int q = 0; q < 4; q++) {
        float4 w = wr[q];
        s += cv[q * 4 + 0] * w.x + cv[q * 4 + 1] * w.y +
             cv[q * 4 + 2] * w.z + cv[q * 4 + 3] * w.w;
    }
    const float v = tanhf(s);

    float r = v;
    #pragma unroll
    for (int off = 16; off; off >>= 1) r += __shfl_down_sync(0xffffffffu, r, off);
    if ((t & 31) == 0) red[t >> 5] = r;
    __syncthreads();
    if (t == 0) {
        float tt = 0.f;
        #pragma unroll
        for (int i = 0; i < 18; i++) tt += red[i];
        smean = tt * (1.0f / 576.0f);
    }
    __syncthreads();

    const float lam = 1.0f / (1.0f + expf(-gamma[o]));
    Wsh[t] = v - lam * smean;
    __syncthreads();

    const int c2 = t / 9;
    const int kk = t - c2 * 9;
    float acc = 0.f;
    #pragma unroll 8
    for (int c = 0; c < CIN; c++)
        acc += Wsh[c * 9 + kk] * value_w[c * CIN + c2];

    g_W2[((size_t)b * KTOT + (c2 * 9 + kk)) * COUT + o] = acc;
}

// ---------------------------------------------------------------------------
// K4: tf32 mma.sync implicit-GEMM conv (3-term precision split).
// Grid (8 rowgroups, 8 batch, 2 ocgroups) = 128 CTAs, 256 threads.
// CTA: 16 image rows (4 iters x 4 rows), N=32 ocs, K=576.
// Warp: one image row half (m = 64 pixels = 4 m16 tiles) x n32 (4 n8 tiles).
// ---------------------------------------------------------------------------
__global__ void __launch_bounds__(256, 1)
k_conv_mma(const float* __restrict__ x, const float* __restrict__ bias,
           float* __restrict__ out) {
    extern __shared__ char smem[];
    uint32_t* tbl2 = (uint32_t*)(smem + OFF_TBL2);
    uint4*    bf4  = (uint4*)(smem + OFF_BF);
    float*    rawf = (float*)(smem + OFF_RAW);

    const int tid  = threadIdx.x;
    const int rg   = blockIdx.x;          // 0..7 (16 rows each)
    const int b    = blockIdx.y;          // 0..7
    const int ocg  = blockIdx.z;          // 0..1
    const int lane = tid & 31;
    const int w    = tid >> 5;            // warp 0..7
    const int tq   = lane & 3;
    const int g    = lane >> 2;

    // --- k -> raw-offset table (packed pairs for k and k+4) ---
    for (int i = tid; i < NKS * 4; i += 256) {
        const int s = i >> 2, q = i & 3;
        const int k0 = s * 8 + q, k1 = k0 + 4;
        const int c0 = k0 / 9, r0_ = k0 - c0 * 9, kh0 = r0_ / 3, kw0 = r0_ - kh0 * 3;
        const int c1 = k1 / 9, r1_ = k1 - c1 * 9, kh1 = r1_ / 3, kw1 = r1_ - kh1 * 3;
        const uint32_t t0 = (uint32_t)((c0 & 15) * NROWS6 + kh0 * RAWC + kw0 + 3);
        const uint32_t t1 = (uint32_t)((c1 & 15) * NROWS6 + kh1 * RAWC + kw1 + 3);
        tbl2[i] = t0 | (t1 << 16);
    }

    // --- B fragments: per (kstep, ntile, lane) uint4 (bh0,bh1,bl0,bl1) ---
    {
        const float* Wb = g_W2 + (size_t)b * KTOT * COUT;
        for (int i = tid; i < NKS * 4 * 32; i += 256) {
            const int ln = i & 31;
            const int j  = (i >> 5) & 3;
            const int s  = i >> 7;
            const int q  = ln & 3;
            const int gg = ln >> 2;
            const int k0 = s * 8 + q;
            const int n  = ocg * 32 + j * 8 + gg;
            const float w0 = Wb[(size_t)k0 * COUT + n];
            const float w1 = Wb[(size_t)(k0 + 4) * COUT + n];
            uint4 v;
            v.x = tf32_rna(w0);
            v.y = tf32_rna(w1);
            v.z = tf32_rna(w0 - __uint_as_float(v.x));
            v.w = tf32_rna(w1 - __uint_as_float(v.y));
            bf4[i] = v;
        }
    }

    // per-thread bias values
    float bs[4][2];
    #pragma unroll
    for (int j = 0; j < 4; j++) {
        const int oc = ocg * 32 + j * 8 + 2 * tq;
        bs[j][0] = bias[oc];
        bs[j][1] = bias[oc + 1];
    }
    __syncthreads();

    const int wrow     = w >> 1;          // 0..3 (row within 4-row iter)
    const int colbase  = (w & 1) * 64;
    const int wrow_off = wrow * RAWC;

    for (int iter = 0; iter < 4; iter++) {
        const int r0 = rg * 16 + iter * 4;

        float acc[4][4][4];
        #pragma unroll
        for (int mt = 0; mt < 4; mt++)
            #pragma unroll
            for (int j = 0; j < 4; j++)
                #pragma unroll
                for (int e = 0; e < 4; e++) acc[mt][j][e] = 0.f;

        for (int sub = 0; sub < 4; sub++) {
            __syncthreads();
            // stage raw x: 16 channels x 6 rows x 136 cols (zero padded)
            const float* xb = x + (size_t)(b * CIN + sub * 16) * (HH * WW);
            for (int i = tid; i < 16 * 6 * 34; i += 256) {
                const int cc  = i / 204;
                const int rem = i - cc * 204;
                const int jj  = rem / 34;
                const int q   = rem - jj * 34;
                float4 v = make_float4(0.f, 0.f, 0.f, 0.f);
                const int ir = r0 - 1 + jj;
                if (q >= 1 && q <= 32 && (unsigned)ir < 128u)
                    v = *(const float4*)(xb + ((size_t)cc * HH + ir) * WW + (q - 1) * 4);
                *(float4*)(rawf + (cc * 6 + jj) * RAWC + q * 4) = v;
            }
            __syncthreads();

            #pragma unroll 1
            for (int ss = 0; ss < 18; ss++) {
                const int s = sub * 18 + ss;
                const uint32_t t01 = tbl2[s * 4 + tq];
                const int o0 = (int)(t01 & 0xffffu) + wrow_off;
                const int o1 = (int)(t01 >> 16) + wrow_off;

                uint4 bfj[4];
                #pragma unroll
                for (int j = 0; j < 4; j++)
                    bfj[j] = bf4[(s * 4 + j) * 32 + lane];

                #pragma unroll
                for (int mt = 0; mt < 4; mt++) {
                    const int cb = colbase + mt * 16 + g;
                    const float a0 = rawf[o0 + cb];
                    const float a1 = rawf[o0 + cb + 8];
                    const float a2 = rawf[o1 + cb];
                    const float a3 = rawf[o1 + cb + 8];
                    const uint32_t ah0 = tf32_rna(a0), ah1 = tf32_rna(a1);
                    const uint32_t ah2 = tf32_rna(a2), ah3 = tf32_rna(a3);
                    const uint32_t al0 = tf32_rna(a0 - __uint_as_float(ah0));
                    const uint32_t al1 = tf32_rna(a1 - __uint_as_float(ah1));
                    const uint32_t al2 = tf32_rna(a2 - __uint_as_float(ah2));
                    const uint32_t al3 = tf32_rna(a3 - __uint_as_float(ah3));
                    #pragma unroll
                    for (int j = 0; j < 4; j++) {
                        mma8(acc[mt][j], ah0, ah1, ah2, ah3, bfj[j].x, bfj[j].y);
                        mma8(acc[mt][j], al0, al1, al2, al3, bfj[j].x, bfj[j].y);
                        mma8(acc[mt][j], ah0, ah1, ah2, ah3, bfj[j].z, bfj[j].w);
                    }
                }
            }
        }

        // epilogue: +bias, ReLU, scalar stores
        const int rw = r0 + wrow;
        #pragma unroll
        for (int mt = 0; mt < 4; mt++) {
            const int cb = colbase + mt * 16 + g;
            #pragma unroll
            for (int j = 0; j < 4; j++) {
                const int oc0 = ocg * 32 + j * 8 + 2 * tq;
                float* p0 = out + (((size_t)(b * COUT + oc0)) * HH + rw) * WW;
                float* p1 = p0 + (size_t)HH * WW;
                p0[cb]     = fmaxf(acc[mt][j][0] + bs[j][0], 0.f);
                p1[cb]     = fmaxf(acc[mt][j][1] + bs[j][1], 0.f);
                p0[cb + 8] = fmaxf(acc[mt][j][2] + bs[j][0], 0.f);
                p1[cb + 8] = fmaxf(acc[mt][j][3] + bs[j][1], 0.f);
            }
        }
    }
}

// ---------------------------------------------------------------------------
// Launch
// ---------------------------------------------------------------------------
extern "C" void kernel_launch(void* const* d_in, const int* in_sizes, int n_in,
                              void* d_out, int out_size) {
    const float* x       = (const float*)d_in[0];
    const float* ctx_w   = (const float*)d_in[1];
    const float* ctx_b   = (const float*)d_in[2];
    const float* kg_w    = (const float*)d_in[3];
    const float* kg_b    = (const float*)d_in[4];
    const float* gamma   = (const float*)d_in[5];
    const float* bias    = (const float*)d_in[6];
    const float* value_w = (const float*)d_in[7];
    float* out = (float*)d_out;

    cudaFuncSetAttribute(k_conv_mma, cudaFuncAttributeMaxDynamicSharedMemorySize,
                         SMEM_TOTAL);

    k_mean<<<NB * CIN, 256>>>(x);
    k_ctx<<<1, 128>>>(ctx_w, ctx_b);
    k_gen<<<NB * COUT, 576>>>(kg_w, kg_b, gamma, value_w);

    dim3 grid(8, NB, 2);
    k_conv_mma<<<grid, 256, SMEM_TOTAL>>>(x, bias, out);
}